// round 13
// baseline (speedup 1.0000x reference)
#include <cuda_runtime.h>
#include <math.h>

#define N_NODES 10000
#define N_EDGES 160000
#define RCUT 1.4415f
#define MAXDEG 96

typedef unsigned long long u64;

__device__ __align__(16) float g_sj[(size_t)N_NODES * 384];   // phase-1 per-node features
__device__ __align__(16) float g_msg2[(size_t)N_NODES * 512]; // phase-2 per-node message

// dst-bucketed edge sources
__device__ int g_deg[N_NODES];
__device__ int g_slots[(size_t)N_NODES * MAXDEG];

// Quad-interleaved packed weights: Wq[c*(2*O) + 2*o + j] = pk(W[(4c+2j)][o], W[(4c+2j+1)][o])
__device__ __align__(16) u64 g_W1q [64 * 128];    // K=128, O=128
__device__ __align__(16) u64 g_W3q [64 * 384];    // K=128, O=384
__device__ __align__(16) u64 g_Uq  [64 * 128];
__device__ __align__(16) u64 g_Vq  [64 * 128];
__device__ __align__(16) u64 g_Wu1q[128 * 128];   // K=256, O=128
__device__ __align__(16) u64 g_Wu2q[64 * 384];    // K=128, O=384
__device__ __align__(16) u64 g_W2q [10 * 384];    // K=20,  O=384 (5 chunks)

__device__ __forceinline__ float silu_f(float v) { return v / (1.0f + __expf(-v)); }

__device__ __forceinline__ void red4(float* p, float a, float b, float c, float d) {
    asm volatile("red.global.add.v4.f32 [%0], {%1,%2,%3,%4};"
                 :: "l"(p), "f"(a), "f"(b), "f"(c), "f"(d) : "memory");
}

// ---- packed f32x2 helpers -------------------------------------------------
__device__ __forceinline__ u64 pk(float x, float y) {
    u64 r; asm("mov.b64 %0, {%1,%2};" : "=l"(r) : "f"(x), "f"(y)); return r;
}
__device__ __forceinline__ u64 f2fma(u64 a, u64 b, u64 c) {
    u64 d; asm("fma.rn.f32x2 %0, %1, %2, %3;" : "=l"(d) : "l"(a), "l"(b), "l"(c)); return d;
}
__device__ __forceinline__ float hsum(u64 a) {
    float lo, hi; asm("mov.b64 {%0,%1}, %2;" : "=f"(lo), "=f"(hi) : "l"(a)); return lo + hi;
}

// ---------------------------------------------------------------------------
// Kernel T: pack weights + zero degree counters.
// ---------------------------------------------------------------------------
__device__ __forceinline__ void packq(u64* dst, const float* W, int O, int idx) {
    int c = idx / (2 * O);
    int rem = idx - c * 2 * O;
    int o = rem >> 1, j = rem & 1;
    int k0 = 4 * c + 2 * j;
    dst[idx] = pk(W[(size_t)k0 * O + o], W[(size_t)(k0 + 1) * O + o]);
}
#define KT_TOTAL (8192 + 24576 + 8192 + 8192 + 16384 + 24576 + 3840)
__global__ __launch_bounds__(256) void kT(const float* __restrict__ W1,
                                          const float* __restrict__ W3,
                                          const float* __restrict__ U,
                                          const float* __restrict__ V,
                                          const float* __restrict__ Wu1,
                                          const float* __restrict__ Wu2,
                                          const float* __restrict__ W2) {
    int idx = blockIdx.x * 256 + threadIdx.x;
    if (idx < N_NODES) g_deg[idx] = 0;
    if (idx >= KT_TOTAL) return;
    if (idx < 8192)  { packq(g_W1q,  W1,  128, idx); return; }  idx -= 8192;
    if (idx < 24576) { packq(g_W3q,  W3,  384, idx); return; }  idx -= 24576;
    if (idx < 8192)  { packq(g_Uq,   U,   128, idx); return; }  idx -= 8192;
    if (idx < 8192)  { packq(g_Vq,   V,   128, idx); return; }  idx -= 8192;
    if (idx < 16384) { packq(g_Wu1q, Wu1, 128, idx); return; }  idx -= 16384;
    if (idx < 24576) { packq(g_Wu2q, Wu2, 384, idx); return; }  idx -= 24576;
    packq(g_W2q, W2, 384, idx);
}

// ---------------------------------------------------------------------------
// Kernel S: bucket edge srcs by dst.
// ---------------------------------------------------------------------------
__global__ __launch_bounds__(256) void kS(const int* __restrict__ ei) {
    int e = blockIdx.x * 256 + threadIdx.x;
    if (e >= N_EDGES) return;
    int dst = ei[N_EDGES + e];
    int pos = atomicAdd(&g_deg[dst], 1);
    g_slots[(size_t)dst * MAXDEG + pos] = ei[e];   // store src
}

// ---------------------------------------------------------------------------
// Kernel A: per-node  g_sj = silu(x[:,384:] @ W1 + b1) @ W3 + b3
// ---------------------------------------------------------------------------
__global__ __launch_bounds__(256) void kA(const float* __restrict__ x,
                                          const float* __restrict__ b1,
                                          const float* __restrict__ b3) {
    __shared__ __align__(16) float s_in[16][128];
    __shared__ __align__(16) float t[16][128];
    const int tid = threadIdx.x;
    const int nb  = blockIdx.x * 16;

    for (int idx = tid; idx < 16 * 32; idx += 256) {
        int m = idx >> 5, c = (idx & 31) * 4;
        *(float4*)&s_in[m][c] = *(const float4*)(x + (size_t)(nb + m) * 512 + 384 + c);
    }
    __syncthreads();

    const int g = tid >> 7;
    const int o = tid & 127;

    {
        u64 acc[8];
        u64 init = pk(b1[o], 0.0f);
#pragma unroll
        for (int j = 0; j < 8; j++) acc[j] = init;
#pragma unroll 2
        for (int k = 0; k < 128; k += 4) {
            ulonglong2 w = *(const ulonglong2*)&g_W1q[(k >> 2) * 256 + 2 * o];
#pragma unroll
            for (int j = 0; j < 8; j++) {
                float4 s = *(const float4*)&s_in[g * 8 + j][k];
                acc[j] = f2fma(pk(s.x, s.y), w.x, acc[j]);
                acc[j] = f2fma(pk(s.z, s.w), w.y, acc[j]);
            }
        }
#pragma unroll
        for (int j = 0; j < 8; j++) t[g * 8 + j][o] = silu_f(hsum(acc[j]));
    }
    __syncthreads();

    {
        u64 a2[8][3];
#pragma unroll
        for (int p = 0; p < 3; p++) {
            u64 init = pk(b3[o + 128 * p], 0.0f);
#pragma unroll
            for (int j = 0; j < 8; j++) a2[j][p] = init;
        }
#pragma unroll 2
        for (int k = 0; k < 128; k += 4) {
            ulonglong2 wp[3];
#pragma unroll
            for (int p = 0; p < 3; p++)
                wp[p] = *(const ulonglong2*)&g_W3q[(k >> 2) * 768 + 2 * (o + 128 * p)];
#pragma unroll
            for (int j = 0; j < 8; j++) {
                float4 tv = *(const float4*)&t[g * 8 + j][k];
                u64 t01 = pk(tv.x, tv.y), t23 = pk(tv.z, tv.w);
#pragma unroll
                for (int p = 0; p < 3; p++) {
                    a2[j][p] = f2fma(t01, wp[p].x, a2[j][p]);
                    a2[j][p] = f2fma(t23, wp[p].y, a2[j][p]);
                }
            }
        }
#pragma unroll
        for (int j = 0; j < 8; j++) {
            size_t base = (size_t)(nb + g * 8 + j) * 384;
#pragma unroll
            for (int p = 0; p < 3; p++) g_sj[base + o + 128 * p] = hsum(a2[j][p]);
        }
    }
}

// ---------------------------------------------------------------------------
// Kernel B: fused per-edge phase-1, 64 edges/block via 4 batches of 16.
// 384 threads. W2 register cache filled ONCE per block (amortized 4x).
// ---------------------------------------------------------------------------
__global__ __launch_bounds__(384) void kB(const float* __restrict__ x,
                                          const int* __restrict__ ei,
                                          const float* __restrict__ ea1,
                                          const float* __restrict__ ea2,
                                          const float* __restrict__ b2,
                                          float* __restrict__ out) {
    __shared__ __align__(16) float split[16][384];   // 24 KB
    __shared__ __align__(8)  float rbfc[16][20];
    __shared__ float ea[16][3];
    __shared__ int   srcs[16], dsts[16];

    const int tid = threadIdx.x;
    const int o   = tid;   // 0..383

    // W2 register cache: once per block, reused over 64 edges.
    u64 w2p[10];
#pragma unroll
    for (int c = 0; c < 5; c++) {
        ulonglong2 w = *(const ulonglong2*)&g_W2q[c * 768 + 2 * o];
        w2p[2 * c] = w.x; w2p[2 * c + 1] = w.y;
    }
    const u64 b2p = pk(b2[o], 0.0f);

    // Hoisted pass-2 thread constants: stride 384 ≡ 0 (mod 128) → q invariant.
    const int q = tid & 127;
    const int estart = tid >> 7;           // 0..2
    const bool isv = (q < 96);
    int iq[4], kq[4], i0 = 0;
    if (isv) {
        int j0 = 4 * q;
#pragma unroll
        for (int t = 0; t < 4; t++) { iq[t] = (j0 + t) / 3; kq[t] = (j0 + t) - 3 * iq[t]; }
    } else {
        i0 = 4 * (q - 96);
    }

#pragma unroll 1
    for (int batch = 0; batch < 4; batch++) {
        const int e0 = blockIdx.x * 64 + batch * 16;
        __syncthreads();   // previous batch's pass-2 reads done before overwrite

        if (tid < 16) {
            srcs[tid] = ei[e0 + tid];
            dsts[tid] = ei[N_EDGES + e0 + tid];
        }
        if (tid >= 32 && tid < 80) {
            int t2 = tid - 32;
            int e = t2 / 3, k = t2 % 3;
            ea[e][k] = ea1[(size_t)(e0 + e) * 3 + k];
        }
        if (tid >= 64 && tid < 384) {
            int t2 = tid - 64;
            int e = t2 / 20, n = t2 % 20;
            float r  = ea2[e0 + e];
            float rb = sqrtf(2.0f / RCUT) * sinpif((float)(n + 1) * r / RCUT) / r;
            float co = 0.5f * (cospif(r / RCUT) + 1.0f) * (r < RCUT ? 1.0f : 0.0f);
            rbfc[e][n] = rb * co;
        }
        __syncthreads();

        // Pass 1: split[e][o] = s_j[src_e][o] * (rbf_e @ W2 + b2)[o]
#pragma unroll 4
        for (int e = 0; e < 16; e++) {
            u64 acc = b2p;
#pragma unroll
            for (int n = 0; n < 10; n++) {
                u64 r = *(const u64*)&rbfc[e][2 * n];   // direct packed load
                acc = f2fma(r, w2p[n], acc);
            }
            split[e][o] = hsum(acc) * g_sj[(size_t)srcs[e] * 384 + o];
        }
        __syncthreads();

        // Pass 2: scatter. q constant per thread; e strides by 3.
        if (isv) {
            for (int e = estart; e < 16; e += 3) {
                int src = srcs[e], dst = dsts[e];
                const float4 xv = *(const float4*)(x + (size_t)src * 512 + 4 * q);
                float ex = ea[e][0], ey = ea[e][1], ez = ea[e][2];
                float eav[3] = {ex, ey, ez};
                float v0 = xv.x * split[e][iq[0]] + split[e][256 + iq[0]] * eav[kq[0]];
                float v1 = xv.y * split[e][iq[1]] + split[e][256 + iq[1]] * eav[kq[1]];
                float v2 = xv.z * split[e][iq[2]] + split[e][256 + iq[2]] * eav[kq[2]];
                float v3 = xv.w * split[e][iq[3]] + split[e][256 + iq[3]] * eav[kq[3]];
                red4(out + (size_t)dst * 512 + 4 * q, v0, v1, v2, v3);
            }
        } else {
            for (int e = estart; e < 16; e += 3) {
                int dst = dsts[e];
                red4(out + (size_t)dst * 512 + 4 * q,
                     split[e][128 + i0], split[e][128 + i0 + 1],
                     split[e][128 + i0 + 2], split[e][128 + i0 + 3]);
            }
        }
    }
}

// ---------------------------------------------------------------------------
// Kernel C: per-node phase-2 message into g_msg2. (round-10 version, 48 KB)
// ---------------------------------------------------------------------------
__global__ __launch_bounds__(256) void kC(const float* __restrict__ xmid,
                                          const float* __restrict__ bu1,
                                          const float* __restrict__ bu2) {
    __shared__ __align__(16) float vA[8][384];
    __shared__ __align__(16) float vUs[8][384];
    __shared__ __align__(16) float ns[8][256];
    __shared__ __align__(16) float h1[8][128];
    __shared__ __align__(16) float h[8][384];

    const int tid = threadIdx.x;
    const int nb  = blockIdx.x * 8;

    for (int idx = tid; idx < 8 * 96; idx += 256) {
        int m = idx / 96, j = (idx % 96) * 4;
        *(float4*)&vA[m][j] = *(const float4*)(xmid + (size_t)(nb + m) * 512 + j);
    }
    for (int idx = tid; idx < 8 * 32; idx += 256) {
        int m = idx >> 5, i = (idx & 31) * 4;
        *(float4*)&ns[m][128 + i] = *(const float4*)(xmid + (size_t)(nb + m) * 512 + 384 + i);
    }
    __syncthreads();

    const int g = tid >> 7;
    const int o = tid & 127;

    {
        u64 acc[4][3];
#pragma unroll
        for (int j = 0; j < 4; j++)
#pragma unroll
            for (int a = 0; a < 3; a++) acc[j][a] = 0ULL;
#pragma unroll 2
        for (int k = 0; k < 128; k += 4) {
            ulonglong2 w = *(const ulonglong2*)&g_Uq[(k >> 2) * 256 + 2 * o];
#pragma unroll
            for (int j = 0; j < 4; j++) {
                int m = g * 4 + j;
#pragma unroll
                for (int a = 0; a < 3; a++) {
                    float4 s = *(const float4*)&vA[m][a * 128 + k];
                    acc[j][a] = f2fma(pk(s.x, s.y), w.x, acc[j][a]);
                    acc[j][a] = f2fma(pk(s.z, s.w), w.y, acc[j][a]);
                }
            }
        }
#pragma unroll
        for (int j = 0; j < 4; j++)
#pragma unroll
            for (int a = 0; a < 3; a++) vUs[g * 4 + j][a * 128 + o] = hsum(acc[j][a]);
    }
    __syncthreads();

    {
        u64 acc[4][3];
#pragma unroll
        for (int j = 0; j < 4; j++)
#pragma unroll
            for (int a = 0; a < 3; a++) acc[j][a] = 0ULL;
#pragma unroll 2
        for (int k = 0; k < 128; k += 4) {
            ulonglong2 w = *(const ulonglong2*)&g_Vq[(k >> 2) * 256 + 2 * o];
#pragma unroll
            for (int j = 0; j < 4; j++) {
                int m = g * 4 + j;
#pragma unroll
                for (int a = 0; a < 3; a++) {
                    float4 s = *(const float4*)&vUs[m][a * 128 + k];
                    acc[j][a] = f2fma(pk(s.x, s.y), w.x, acc[j][a]);
                    acc[j][a] = f2fma(pk(s.z, s.w), w.y, acc[j][a]);
                }
            }
        }
        __syncthreads();
#pragma unroll
        for (int j = 0; j < 4; j++)
#pragma unroll
            for (int a = 0; a < 3; a++) vA[g * 4 + j][a * 128 + o] = hsum(acc[j][a]);
    }
    __syncthreads();

    for (int idx = tid; idx < 8 * 128; idx += 256) {
        int m = idx >> 7, i = idx & 127;
        float x0 = vA[m][3 * i], x1 = vA[m][3 * i + 1], x2 = vA[m][3 * i + 2];
        ns[m][i] = sqrtf(x0 * x0 + x1 * x1 + x2 * x2);
    }
    __syncthreads();

    {
        u64 acc[4];
        u64 init = pk(bu1[o], 0.0f);
#pragma unroll
        for (int j = 0; j < 4; j++) acc[j] = init;
#pragma unroll 2
        for (int k = 0; k < 256; k += 4) {
            ulonglong2 w = *(const ulonglong2*)&g_Wu1q[(k >> 2) * 256 + 2 * o];
#pragma unroll
            for (int j = 0; j < 4; j++) {
                float4 s = *(const float4*)&ns[g * 4 + j][k];
                acc[j] = f2fma(pk(s.x, s.y), w.x, acc[j]);
                acc[j] = f2fma(pk(s.z, s.w), w.y, acc[j]);
            }
        }
#pragma unroll
        for (int j = 0; j < 4; j++) h1[g * 4 + j][o] = silu_f(hsum(acc[j]));
    }
    __syncthreads();

    {
        u64 acc[4][3];
#pragma unroll
        for (int p = 0; p < 3; p++) {
            u64 init = pk(bu2[o + 128 * p], 0.0f);
#pragma unroll
            for (int j = 0; j < 4; j++) acc[j][p] = init;
        }
#pragma unroll 2
        for (int k = 0; k < 128; k += 4) {
            ulonglong2 wp[3];
#pragma unroll
            for (int p = 0; p < 3; p++)
                wp[p] = *(const ulonglong2*)&g_Wu2q[(k >> 2) * 768 + 2 * (o + 128 * p)];
#pragma unroll
            for (int j = 0; j < 4; j++) {
                float4 tv = *(const float4*)&h1[g * 4 + j][k];
                u64 t01 = pk(tv.x, tv.y), t23 = pk(tv.z, tv.w);
#pragma unroll
                for (int p = 0; p < 3; p++) {
                    acc[j][p] = f2fma(t01, wp[p].x, acc[j][p]);
                    acc[j][p] = f2fma(t23, wp[p].y, acc[j][p]);
                }
            }
        }
#pragma unroll
        for (int j = 0; j < 4; j++)
#pragma unroll
            for (int p = 0; p < 3; p++) h[g * 4 + j][o + 128 * p] = hsum(acc[j][p]);
    }
    __syncthreads();

    for (int idx = tid; idx < 8 * 512; idx += 256) {
        int m = idx >> 9, j = idx & 511;
        float val;
        if (j < 384) {
            val = vUs[m][j] * h[m][j / 3];
        } else {
            int i = j - 384;
            float d = vUs[m][3 * i]     * vA[m][3 * i]
                    + vUs[m][3 * i + 1] * vA[m][3 * i + 1]
                    + vUs[m][3 * i + 2] * vA[m][3 * i + 2];
            val = d * h[m][i] + h[m][256 + i];
        }
        g_msg2[(size_t)(nb + m) * 512 + j] = val;
    }
}

// ---------------------------------------------------------------------------
// Kernel D2: dst-owned segmented sum — no atomics. 2 dsts/block, 256 threads.
// ---------------------------------------------------------------------------
__global__ __launch_bounds__(256) void kD2(float* __restrict__ out) {
    __shared__ int s_slots[2][MAXDEG];
    __shared__ int s_deg[2];

    const int tid = threadIdx.x;
    const int d0  = blockIdx.x * 2;

    if (tid < 2) s_deg[tid] = g_deg[d0 + tid];
    if (tid < 2 * MAXDEG) {
        int d = tid / MAXDEG, i = tid % MAXDEG;
        s_slots[d][i] = g_slots[(size_t)(d0 + d) * MAXDEG + i];
    }
    __syncthreads();

    const int g = tid >> 7, o = tid & 127;
    const int dst = d0 + g;
    const int deg = s_deg[g];

    float4 acc = *(const float4*)(out + (size_t)dst * 512 + 4 * o);
    int i = 0;
    for (; i + 2 <= deg; i += 2) {
        int s0 = s_slots[g][i], s1 = s_slots[g][i + 1];
        float4 v0 = *(const float4*)(g_msg2 + (size_t)s0 * 512 + 4 * o);
        float4 v1 = *(const float4*)(g_msg2 + (size_t)s1 * 512 + 4 * o);
        acc.x += v0.x; acc.y += v0.y; acc.z += v0.z; acc.w += v0.w;
        acc.x += v1.x; acc.y += v1.y; acc.z += v1.z; acc.w += v1.w;
    }
    if (i < deg) {
        int s0 = s_slots[g][i];
        float4 v0 = *(const float4*)(g_msg2 + (size_t)s0 * 512 + 4 * o);
        acc.x += v0.x; acc.y += v0.y; acc.z += v0.z; acc.w += v0.w;
    }
    *(float4*)(out + (size_t)dst * 512 + 4 * o) = acc;
}

// ---------------------------------------------------------------------------
extern "C" void kernel_launch(void* const* d_in, const int* in_sizes, int n_in,
                              void* d_out, int out_size) {
    const float* x   = (const float*)d_in[0];
    const int*   ei  = (const int*)d_in[1];     // int32 (jax x64 disabled)
    const float* ea1 = (const float*)d_in[2];
    const float* ea2 = (const float*)d_in[3];
    const float* W1  = (const float*)d_in[4];
    const float* b1  = (const float*)d_in[5];
    const float* W2  = (const float*)d_in[6];
    const float* b2  = (const float*)d_in[7];
    const float* W3  = (const float*)d_in[8];
    const float* b3  = (const float*)d_in[9];
    const float* U   = (const float*)d_in[10];
    const float* V   = (const float*)d_in[11];
    const float* Wu1 = (const float*)d_in[12];
    const float* bu1 = (const float*)d_in[13];
    const float* Wu2 = (const float*)d_in[14];
    const float* bu2 = (const float*)d_in[15];
    float* out = (float*)d_out;

    cudaMemcpyAsync(out, x, (size_t)N_NODES * 512 * sizeof(float),
                    cudaMemcpyDeviceToDevice);

    kT<<<(KT_TOTAL + 255) / 256, 256>>>(W1, W3, U, V, Wu1, Wu2, W2);
    kS<<<(N_EDGES + 255) / 256, 256>>>(ei);
    kA<<<N_NODES / 16, 256>>>(x, b1, b3);
    kB<<<N_EDGES / 64, 384>>>(x, ei, ea1, ea2, b2, out);
    kC<<<N_NODES / 8, 256>>>(out, bu1, bu2);
    kD2<<<N_NODES / 2, 256>>>(out);
}

// round 14
// speedup vs baseline: 1.1365x; 1.1365x over previous
#include <cuda_runtime.h>
#include <math.h>

#define N_NODES 10000
#define N_EDGES 160000
#define RCUT 1.4415f
#define MAXDEG 96

typedef unsigned long long u64;

__device__ __align__(16) float g_sj[(size_t)N_NODES * 384];   // phase-1 per-node features
__device__ __align__(16) float g_msg2[(size_t)N_NODES * 512]; // phase-2 per-node message

// dst-bucketed edge sources
__device__ int g_deg[N_NODES];
__device__ int g_slots[(size_t)N_NODES * MAXDEG];

// Quad-interleaved packed weights: Wq[c*(2*O) + 2*o + j] = pk(W[(4c+2j)][o], W[(4c+2j+1)][o])
__device__ __align__(16) u64 g_W1q [64 * 128];    // K=128, O=128
__device__ __align__(16) u64 g_W3q [64 * 384];    // K=128, O=384
__device__ __align__(16) u64 g_Uq  [64 * 128];
__device__ __align__(16) u64 g_Vq  [64 * 128];
__device__ __align__(16) u64 g_Wu1q[128 * 128];   // K=256, O=128
__device__ __align__(16) u64 g_Wu2q[64 * 384];    // K=128, O=384
__device__ __align__(16) u64 g_W2q [10 * 384];    // K=20,  O=384 (5 chunks)

__device__ __forceinline__ float silu_f(float v) { return v / (1.0f + __expf(-v)); }

__device__ __forceinline__ void red4(float* p, float a, float b, float c, float d) {
    asm volatile("red.global.add.v4.f32 [%0], {%1,%2,%3,%4};"
                 :: "l"(p), "f"(a), "f"(b), "f"(c), "f"(d) : "memory");
}

// ---- packed f32x2 helpers -------------------------------------------------
__device__ __forceinline__ u64 pk(float x, float y) {
    u64 r; asm("mov.b64 %0, {%1,%2};" : "=l"(r) : "f"(x), "f"(y)); return r;
}
__device__ __forceinline__ u64 f2fma(u64 a, u64 b, u64 c) {
    u64 d; asm("fma.rn.f32x2 %0, %1, %2, %3;" : "=l"(d) : "l"(a), "l"(b), "l"(c)); return d;
}
__device__ __forceinline__ float hsum(u64 a) {
    float lo, hi; asm("mov.b64 {%0,%1}, %2;" : "=f"(lo), "=f"(hi) : "l"(a)); return lo + hi;
}

// ---------------------------------------------------------------------------
// Kernel T: pack weights + zero degree counters.
// ---------------------------------------------------------------------------
__device__ __forceinline__ void packq(u64* dst, const float* W, int O, int idx) {
    int c = idx / (2 * O);
    int rem = idx - c * 2 * O;
    int o = rem >> 1, j = rem & 1;
    int k0 = 4 * c + 2 * j;
    dst[idx] = pk(W[(size_t)k0 * O + o], W[(size_t)(k0 + 1) * O + o]);
}
#define KT_TOTAL (8192 + 24576 + 8192 + 8192 + 16384 + 24576 + 3840)
__global__ __launch_bounds__(256) void kT(const float* __restrict__ W1,
                                          const float* __restrict__ W3,
                                          const float* __restrict__ U,
                                          const float* __restrict__ V,
                                          const float* __restrict__ Wu1,
                                          const float* __restrict__ Wu2,
                                          const float* __restrict__ W2) {
    int idx = blockIdx.x * 256 + threadIdx.x;
    if (idx < N_NODES) g_deg[idx] = 0;
    if (idx >= KT_TOTAL) return;
    if (idx < 8192)  { packq(g_W1q,  W1,  128, idx); return; }  idx -= 8192;
    if (idx < 24576) { packq(g_W3q,  W3,  384, idx); return; }  idx -= 24576;
    if (idx < 8192)  { packq(g_Uq,   U,   128, idx); return; }  idx -= 8192;
    if (idx < 8192)  { packq(g_Vq,   V,   128, idx); return; }  idx -= 8192;
    if (idx < 16384) { packq(g_Wu1q, Wu1, 128, idx); return; }  idx -= 16384;
    if (idx < 24576) { packq(g_Wu2q, Wu2, 384, idx); return; }  idx -= 24576;
    packq(g_W2q, W2, 384, idx);
}

// ---------------------------------------------------------------------------
// Kernel A: per-node  g_sj = silu(x[:,384:] @ W1 + b1) @ W3 + b3
// Also: residual copy out=x for its 16 rows, and dst-bucketing (1 edge/thread;
// grid 625 x 256 = exactly N_EDGES threads).
// ---------------------------------------------------------------------------
__global__ __launch_bounds__(256) void kA(const float* __restrict__ x,
                                          const int* __restrict__ ei,
                                          const float* __restrict__ b1,
                                          const float* __restrict__ b3,
                                          float* __restrict__ out) {
    __shared__ __align__(16) float s_in[16][128];
    __shared__ __align__(16) float t[16][128];
    const int tid = threadIdx.x;
    const int nb  = blockIdx.x * 16;

    // Edge bucketing (replaces kS): one edge per thread.
    {
        int e = blockIdx.x * 256 + tid;
        int dst = ei[N_EDGES + e];
        int pos = atomicAdd(&g_deg[dst], 1);
        g_slots[(size_t)dst * MAXDEG + pos] = ei[e];
    }

    // Residual copy (replaces memcpy): 16 rows x 512 floats = 2048 float4.
    {
        const float4* xs = (const float4*)(x + (size_t)nb * 512);
        float4* os = (float4*)(out + (size_t)nb * 512);
        for (int i = tid; i < 2048; i += 256) os[i] = xs[i];
    }

    for (int idx = tid; idx < 16 * 32; idx += 256) {
        int m = idx >> 5, c = (idx & 31) * 4;
        *(float4*)&s_in[m][c] = *(const float4*)(x + (size_t)(nb + m) * 512 + 384 + c);
    }
    __syncthreads();

    const int g = tid >> 7;
    const int o = tid & 127;

    {
        u64 acc[8];
        u64 init = pk(b1[o], 0.0f);
#pragma unroll
        for (int j = 0; j < 8; j++) acc[j] = init;
#pragma unroll 2
        for (int k = 0; k < 128; k += 4) {
            ulonglong2 w = *(const ulonglong2*)&g_W1q[(k >> 2) * 256 + 2 * o];
#pragma unroll
            for (int j = 0; j < 8; j++) {
                float4 s = *(const float4*)&s_in[g * 8 + j][k];
                acc[j] = f2fma(pk(s.x, s.y), w.x, acc[j]);
                acc[j] = f2fma(pk(s.z, s.w), w.y, acc[j]);
            }
        }
#pragma unroll
        for (int j = 0; j < 8; j++) t[g * 8 + j][o] = silu_f(hsum(acc[j]));
    }
    __syncthreads();

    {
        u64 a2[8][3];
#pragma unroll
        for (int p = 0; p < 3; p++) {
            u64 init = pk(b3[o + 128 * p], 0.0f);
#pragma unroll
            for (int j = 0; j < 8; j++) a2[j][p] = init;
        }
#pragma unroll 2
        for (int k = 0; k < 128; k += 4) {
            ulonglong2 wp[3];
#pragma unroll
            for (int p = 0; p < 3; p++)
                wp[p] = *(const ulonglong2*)&g_W3q[(k >> 2) * 768 + 2 * (o + 128 * p)];
#pragma unroll
            for (int j = 0; j < 8; j++) {
                float4 tv = *(const float4*)&t[g * 8 + j][k];
                u64 t01 = pk(tv.x, tv.y), t23 = pk(tv.z, tv.w);
#pragma unroll
                for (int p = 0; p < 3; p++) {
                    a2[j][p] = f2fma(t01, wp[p].x, a2[j][p]);
                    a2[j][p] = f2fma(t23, wp[p].y, a2[j][p]);
                }
            }
        }
#pragma unroll
        for (int j = 0; j < 8; j++) {
            size_t base = (size_t)(nb + g * 8 + j) * 384;
#pragma unroll
            for (int p = 0; p < 3; p++) g_sj[base + o + 128 * p] = hsum(a2[j][p]);
        }
    }
}

// ---------------------------------------------------------------------------
// Kernel B: fused per-edge phase-1 (basis GEMM in smem + message + scatter).
// 16 edges/block, 384 threads. (round-10 version + direct u64 rbfc loads)
// ---------------------------------------------------------------------------
__global__ __launch_bounds__(384) void kB(const float* __restrict__ x,
                                          const int* __restrict__ ei,
                                          const float* __restrict__ ea1,
                                          const float* __restrict__ ea2,
                                          const float* __restrict__ b2,
                                          float* __restrict__ out) {
    __shared__ __align__(16) float split[16][384];   // 24 KB
    __shared__ __align__(8)  float rbfc[16][20];
    __shared__ float ea[16][3];
    __shared__ int   srcs[16], dsts[16];

    const int tid = threadIdx.x;
    const int e0  = blockIdx.x * 16;

    if (tid < 16) {
        srcs[tid] = ei[e0 + tid];
        dsts[tid] = ei[N_EDGES + e0 + tid];
    }
    if (tid >= 32 && tid < 80) {
        int q = tid - 32;
        int e = q / 3, k = q % 3;
        ea[e][k] = ea1[(size_t)(e0 + e) * 3 + k];
    }
    if (tid >= 64 && tid < 384) {
        int q = tid - 64;
        int e = q / 20, n = q % 20;
        float r  = ea2[e0 + e];
        float rb = sqrtf(2.0f / RCUT) * sinpif((float)(n + 1) * r / RCUT) / r;
        float co = 0.5f * (cospif(r / RCUT) + 1.0f) * (r < RCUT ? 1.0f : 0.0f);
        rbfc[e][n] = rb * co;
    }

    const int o = tid;   // 0..383
    u64 w2p[10];
#pragma unroll
    for (int c = 0; c < 5; c++) {
        ulonglong2 w = *(const ulonglong2*)&g_W2q[c * 768 + 2 * o];
        w2p[2 * c] = w.x; w2p[2 * c + 1] = w.y;
    }
    const u64 b2p = pk(b2[o], 0.0f);
    __syncthreads();

#pragma unroll 4
    for (int e = 0; e < 16; e++) {
        u64 acc = b2p;
#pragma unroll
        for (int n = 0; n < 10; n++) {
            u64 r = *(const u64*)&rbfc[e][2 * n];   // direct packed LDS.64
            acc = f2fma(r, w2p[n], acc);
        }
        split[e][o] = hsum(acc) * g_sj[(size_t)srcs[e] * 384 + o];
    }
    __syncthreads();

    for (int idx = tid; idx < 16 * 128; idx += 384) {
        int e = idx >> 7, q = idx & 127;
        int src = srcs[e], dst = dsts[e];
        float v0, v1, v2, v3;
        if (q < 96) {
            int j0 = 4 * q;
            const float4 xv = *(const float4*)(x + (size_t)src * 512 + j0);
            float xs[4] = {xv.x, xv.y, xv.z, xv.w};
            float vals[4];
#pragma unroll
            for (int tq = 0; tq < 4; tq++) {
                int j = j0 + tq;
                int i = j / 3;
                int k = j - 3 * i;
                vals[tq] = xs[tq] * split[e][i] + split[e][256 + i] * ea[e][k];
            }
            v0 = vals[0]; v1 = vals[1]; v2 = vals[2]; v3 = vals[3];
        } else {
            int i0 = 4 * (q - 96);
            v0 = split[e][128 + i0];
            v1 = split[e][128 + i0 + 1];
            v2 = split[e][128 + i0 + 2];
            v3 = split[e][128 + i0 + 3];
        }
        red4(out + (size_t)dst * 512 + 4 * q, v0, v1, v2, v3);
    }
}

// ---------------------------------------------------------------------------
// Kernel C: per-node phase-2 message into g_msg2. (round-10 version, 48 KB)
// ---------------------------------------------------------------------------
__global__ __launch_bounds__(256) void kC(const float* __restrict__ xmid,
                                          const float* __restrict__ bu1,
                                          const float* __restrict__ bu2) {
    __shared__ __align__(16) float vA[8][384];
    __shared__ __align__(16) float vUs[8][384];
    __shared__ __align__(16) float ns[8][256];
    __shared__ __align__(16) float h1[8][128];
    __shared__ __align__(16) float h[8][384];

    const int tid = threadIdx.x;
    const int nb  = blockIdx.x * 8;

    for (int idx = tid; idx < 8 * 96; idx += 256) {
        int m = idx / 96, j = (idx % 96) * 4;
        *(float4*)&vA[m][j] = *(const float4*)(xmid + (size_t)(nb + m) * 512 + j);
    }
    for (int idx = tid; idx < 8 * 32; idx += 256) {
        int m = idx >> 5, i = (idx & 31) * 4;
        *(float4*)&ns[m][128 + i] = *(const float4*)(xmid + (size_t)(nb + m) * 512 + 384 + i);
    }
    __syncthreads();

    const int g = tid >> 7;
    const int o = tid & 127;

    {
        u64 acc[4][3];
#pragma unroll
        for (int j = 0; j < 4; j++)
#pragma unroll
            for (int a = 0; a < 3; a++) acc[j][a] = 0ULL;
#pragma unroll 2
        for (int k = 0; k < 128; k += 4) {
            ulonglong2 w = *(const ulonglong2*)&g_Uq[(k >> 2) * 256 + 2 * o];
#pragma unroll
            for (int j = 0; j < 4; j++) {
                int m = g * 4 + j;
#pragma unroll
                for (int a = 0; a < 3; a++) {
                    float4 s = *(const float4*)&vA[m][a * 128 + k];
                    acc[j][a] = f2fma(pk(s.x, s.y), w.x, acc[j][a]);
                    acc[j][a] = f2fma(pk(s.z, s.w), w.y, acc[j][a]);
                }
            }
        }
#pragma unroll
        for (int j = 0; j < 4; j++)
#pragma unroll
            for (int a = 0; a < 3; a++) vUs[g * 4 + j][a * 128 + o] = hsum(acc[j][a]);
    }
    __syncthreads();

    {
        u64 acc[4][3];
#pragma unroll
        for (int j = 0; j < 4; j++)
#pragma unroll
            for (int a = 0; a < 3; a++) acc[j][a] = 0ULL;
#pragma unroll 2
        for (int k = 0; k < 128; k += 4) {
            ulonglong2 w = *(const ulonglong2*)&g_Vq[(k >> 2) * 256 + 2 * o];
#pragma unroll
            for (int j = 0; j < 4; j++) {
                int m = g * 4 + j;
#pragma unroll
                for (int a = 0; a < 3; a++) {
                    float4 s = *(const float4*)&vUs[m][a * 128 + k];
                    acc[j][a] = f2fma(pk(s.x, s.y), w.x, acc[j][a]);
                    acc[j][a] = f2fma(pk(s.z, s.w), w.y, acc[j][a]);
                }
            }
        }
        __syncthreads();
#pragma unroll
        for (int j = 0; j < 4; j++)
#pragma unroll
            for (int a = 0; a < 3; a++) vA[g * 4 + j][a * 128 + o] = hsum(acc[j][a]);
    }
    __syncthreads();

    for (int idx = tid; idx < 8 * 128; idx += 256) {
        int m = idx >> 7, i = idx & 127;
        float x0 = vA[m][3 * i], x1 = vA[m][3 * i + 1], x2 = vA[m][3 * i + 2];
        ns[m][i] = sqrtf(x0 * x0 + x1 * x1 + x2 * x2);
    }
    __syncthreads();

    {
        u64 acc[4];
        u64 init = pk(bu1[o], 0.0f);
#pragma unroll
        for (int j = 0; j < 4; j++) acc[j] = init;
#pragma unroll 2
        for (int k = 0; k < 256; k += 4) {
            ulonglong2 w = *(const ulonglong2*)&g_Wu1q[(k >> 2) * 256 + 2 * o];
#pragma unroll
            for (int j = 0; j < 4; j++) {
                float4 s = *(const float4*)&ns[g * 4 + j][k];
                acc[j] = f2fma(pk(s.x, s.y), w.x, acc[j]);
                acc[j] = f2fma(pk(s.z, s.w), w.y, acc[j]);
            }
        }
#pragma unroll
        for (int j = 0; j < 4; j++) h1[g * 4 + j][o] = silu_f(hsum(acc[j]));
    }
    __syncthreads();

    {
        u64 acc[4][3];
#pragma unroll
        for (int p = 0; p < 3; p++) {
            u64 init = pk(bu2[o + 128 * p], 0.0f);
#pragma unroll
            for (int j = 0; j < 4; j++) acc[j][p] = init;
        }
#pragma unroll 2
        for (int k = 0; k < 128; k += 4) {
            ulonglong2 wp[3];
#pragma unroll
            for (int p = 0; p < 3; p++)
                wp[p] = *(const ulonglong2*)&g_Wu2q[(k >> 2) * 768 + 2 * (o + 128 * p)];
#pragma unroll
            for (int j = 0; j < 4; j++) {
                float4 tv = *(const float4*)&h1[g * 4 + j][k];
                u64 t01 = pk(tv.x, tv.y), t23 = pk(tv.z, tv.w);
#pragma unroll
                for (int p = 0; p < 3; p++) {
                    acc[j][p] = f2fma(t01, wp[p].x, acc[j][p]);
                    acc[j][p] = f2fma(t23, wp[p].y, acc[j][p]);
                }
            }
        }
#pragma unroll
        for (int j = 0; j < 4; j++)
#pragma unroll
            for (int p = 0; p < 3; p++) h[g * 4 + j][o + 128 * p] = hsum(acc[j][p]);
    }
    __syncthreads();

    for (int idx = tid; idx < 8 * 512; idx += 256) {
        int m = idx >> 9, j = idx & 511;
        float val;
        if (j < 384) {
            val = vUs[m][j] * h[m][j / 3];
        } else {
            int i = j - 384;
            float d = vUs[m][3 * i]     * vA[m][3 * i]
                    + vUs[m][3 * i + 1] * vA[m][3 * i + 1]
                    + vUs[m][3 * i + 2] * vA[m][3 * i + 2];
            val = d * h[m][i] + h[m][256 + i];
        }
        g_msg2[(size_t)(nb + m) * 512 + j] = val;
    }
}

// ---------------------------------------------------------------------------
// Kernel D2: dst-owned segmented sum — no atomics. 2 dsts/block, 256 threads.
// ---------------------------------------------------------------------------
__global__ __launch_bounds__(256) void kD2(float* __restrict__ out) {
    __shared__ int s_slots[2][MAXDEG];
    __shared__ int s_deg[2];

    const int tid = threadIdx.x;
    const int d0  = blockIdx.x * 2;

    if (tid < 2) s_deg[tid] = g_deg[d0 + tid];
    if (tid < 2 * MAXDEG) {
        int d = tid / MAXDEG, i = tid % MAXDEG;
        s_slots[d][i] = g_slots[(size_t)(d0 + d) * MAXDEG + i];
    }
    __syncthreads();

    const int g = tid >> 7, o = tid & 127;
    const int dst = d0 + g;
    const int deg = s_deg[g];

    float4 acc = *(const float4*)(out + (size_t)dst * 512 + 4 * o);
    int i = 0;
    for (; i + 2 <= deg; i += 2) {
        int s0 = s_slots[g][i], s1 = s_slots[g][i + 1];
        float4 v0 = *(const float4*)(g_msg2 + (size_t)s0 * 512 + 4 * o);
        float4 v1 = *(const float4*)(g_msg2 + (size_t)s1 * 512 + 4 * o);
        acc.x += v0.x; acc.y += v0.y; acc.z += v0.z; acc.w += v0.w;
        acc.x += v1.x; acc.y += v1.y; acc.z += v1.z; acc.w += v1.w;
    }
    if (i < deg) {
        int s0 = s_slots[g][i];
        float4 v0 = *(const float4*)(g_msg2 + (size_t)s0 * 512 + 4 * o);
        acc.x += v0.x; acc.y += v0.y; acc.z += v0.z; acc.w += v0.w;
    }
    *(float4*)(out + (size_t)dst * 512 + 4 * o) = acc;
}

// ---------------------------------------------------------------------------
extern "C" void kernel_launch(void* const* d_in, const int* in_sizes, int n_in,
                              void* d_out, int out_size) {
    const float* x   = (const float*)d_in[0];
    const int*   ei  = (const int*)d_in[1];     // int32 (jax x64 disabled)
    const float* ea1 = (const float*)d_in[2];
    const float* ea2 = (const float*)d_in[3];
    const float* W1  = (const float*)d_in[4];
    const float* b1  = (const float*)d_in[5];
    const float* W2  = (const float*)d_in[6];
    const float* b2  = (const float*)d_in[7];
    const float* W3  = (const float*)d_in[8];
    const float* b3  = (const float*)d_in[9];
    const float* U   = (const float*)d_in[10];
    const float* V   = (const float*)d_in[11];
    const float* Wu1 = (const float*)d_in[12];
    const float* bu1 = (const float*)d_in[13];
    const float* Wu2 = (const float*)d_in[14];
    const float* bu2 = (const float*)d_in[15];
    float* out = (float*)d_out;

    kT<<<(KT_TOTAL + 255) / 256, 256>>>(W1, W3, U, V, Wu1, Wu2, W2);
    kA<<<N_NODES / 16, 256>>>(x, ei, b1, b3, out);   // also: out=x copy + edge bucketing
    kB<<<N_EDGES / 16, 384>>>(x, ei, ea1, ea2, b2, out);
    kC<<<N_NODES / 8, 256>>>(out, bu1, bu2);
    kD2<<<N_NODES / 2, 256>>>(out);
}